// round 17
// baseline (speedup 1.0000x reference)
#include <cuda_runtime.h>

// Problem shape (fixed by reference): B=256 students, T=200 steps, Q=1000 questions.
#define NB 256
#define NT 200
#define NQ 1000
#define TM1 (NT - 1)   // 199

// Scratch (no cudaMalloc allowed).
__device__ float        g_student_loss[NB];
__device__ unsigned int g_arrive = 0;   // self-resetting ticket

// BCE(sigmoid(x), a) = softplus(x) - a*x, softplus via stable form.
__device__ __forceinline__ float bce_from_logit(float x, float a) {
    float sp = fmaxf(x, 0.0f) + __logf(1.0f + __expf(-fabsf(x)));
    return sp - a * x;
}

// Release+acquire L2 atomic ticket: orders the preceding __stcg without a
// full gpu-scope MEMBAR / L1 flush (R2's cost).
__device__ __forceinline__ unsigned int ticket_acq_rel(unsigned int* p) {
    unsigned int old;
    asm volatile("atom.add.acq_rel.gpu.global.u32 %0, [%1], 1;"
                 : "=r"(old) : "l"(p) : "memory");
    return old;
}

__global__ __launch_bounds__(256)
void fused_loss_kernel(const float* __restrict__ logit_c,
                       const float* __restrict__ logit_t,
                       const int*   __restrict__ q_idx,
                       const int*   __restrict__ correct,
                       float*       __restrict__ out) {
    const int b    = blockIdx.x;    // student
    const int t    = threadIdx.x;   // step 0..TM1-1 (threads >= TM1 idle)
    const int lane = t & 31;
    const int warp = t >> 5;

    __shared__ int   s_i[8];
    __shared__ float s_f[8];
    __shared__ float s_e[256];      // raw per-step losses (slow-path only)
    __shared__ int   s_is_last;

    float e = 0.0f, pc = 0.0f;
    int   idx = -1;
    const bool active = (t < TM1);

    if (active) {
        const int   q    = q_idx[b * NT + t + 1];
        const float a    = (float)correct[b * NT + t + 1];
        const long  base = ((long)b * NT + t) * NQ;
        const float xc = __ldg(&logit_c[base + q]);
        const float xt = __ldg(&logit_t[base + q]);
        pc = 1.0f / (1.0f + __expf(-xc));
        const float pt = 1.0f / (1.0f + __expf(-xt));
        out[1 + b * TM1 + t]            = 0.5f * (pt + pc);  // p_mean
        out[1 + NB * TM1 + b * TM1 + t] = a;                 // ground_truth
        e   = bce_from_logit(xc, a) + bce_from_logit(xt, a);
        idx = (pc > 0.0f) ? t : -1;                          // reference trim
    }
    s_e[t] = e;

    // ---- single fused reduction: max(idx) and sum(e) together ----
    float se = e;
    #pragma unroll
    for (int o = 16; o; o >>= 1) {
        se  += __shfl_xor_sync(0xffffffffu, se, o);
        idx  = max(idx, __shfl_xor_sync(0xffffffffu, idx, o));
    }
    if (lane == 0) { s_f[warp] = se; s_i[warp] = idx; }
    __syncthreads();

    if (t == 0) {
        int   last = s_i[0];
        float sum  = s_f[0];
        #pragma unroll
        for (int i = 1; i < 8; i++) { last = max(last, s_i[i]); sum += s_f[i]; }
        if (last < 0) last = TM1 - 1;             // all-invalid -> full mask (ref)
        if (last != TM1 - 1) {                    // trim actually trims: recompute
            sum = 0.0f;
            for (int j = 0; j <= last; j++) sum += s_e[j];
        }
        // L2-visible store (bypass L1), then release ticket.
        __stcg(&g_student_loss[b], sum / (float)(last + 1));
        s_is_last = (ticket_acq_rel(&g_arrive) == NB - 1);
    }
    __syncthreads();

    // ---- last-arriving block: deterministic fixed-order final sum ----
    if (s_is_last) {
        float v = __ldcg(&g_student_loss[t]);   // NB == 256 == blockDim
        #pragma unroll
        for (int o = 16; o; o >>= 1) v += __shfl_xor_sync(0xffffffffu, v, o);
        if (lane == 0) s_f[warp] = v;
        __syncthreads();
        if (t == 0) {
            float s = 0.0f;
            #pragma unroll
            for (int i = 0; i < 8; i++) s += s_f[i];
            out[0]   = s;
            g_arrive = 0;   // reset for next graph replay
        }
    }
}

extern "C" void kernel_launch(void* const* d_in, const int* in_sizes, int n_in,
                              void* d_out, int out_size) {
    const float* logit_c = (const float*)d_in[0];
    const float* logit_t = (const float*)d_in[1];
    const int*   q_idx   = (const int*)d_in[2];
    const int*   correct = (const int*)d_in[3];
    float* out = (float*)d_out;

    fused_loss_kernel<<<NB, 256>>>(logit_c, logit_t, q_idx, correct, out);
}